// round 14
// baseline (speedup 1.0000x reference)
#include <cuda_runtime.h>
#include <cuda_fp16.h>
#include <math.h>
#include <stdint.h>

// Problem constants
#define BB 4
#define TT 2048
#define CC 1024
#define HH 16
#define DHD 64
#define MM (BB*TT)          // 8192 rows

// Scratch (allocation-free rule: __device__ globals)
__device__ __half g_x16[MM*CC];          // x in fp16
__device__ __half g_Q16[BB*HH*TT*DHD];   // Q [B,H,T,Dh] fp16, scaled 0.125*log2(e)
__device__ __half g_K16[BB*HH*TT*DHD];
__device__ __half g_V16[BB*HH*TT*DHD];
__device__ __half g_O16[MM*CC];          // attention out [B,T,C] fp16
__device__ __half g_Wq16[3072*1024];     // W_qkv^T [N,K] fp16
__device__ __half g_Wo16[1024*1024];     // W_out^T [N,K] fp16

// ---------------------------------------------------------------------------
// helpers
// ---------------------------------------------------------------------------
__device__ __forceinline__ uint32_t smem_u32(const void* p) {
    uint32_t a;
    asm("{ .reg .u64 t; cvta.to.shared.u64 t, %1; cvt.u32.u64 %0, t; }"
        : "=r"(a) : "l"(p));
    return a;
}
__device__ __forceinline__ void cp16(uint32_t s, const void* g) {
    asm volatile("cp.async.cg.shared.global [%0], [%1], 16;" :: "r"(s), "l"(g));
}
#define CP_COMMIT() asm volatile("cp.async.commit_group;" ::: "memory")
#define CP_WAIT(n)  asm volatile("cp.async.wait_group %0;" :: "n"(n) : "memory")

__device__ __forceinline__ void mma_f16(float c[4], const unsigned a[4],
                                        const unsigned b0, const unsigned b1) {
    asm volatile(
        "mma.sync.aligned.m16n8k16.row.col.f32.f16.f16.f32 "
        "{%0,%1,%2,%3},{%4,%5,%6,%7},{%8,%9},{%0,%1,%2,%3};"
        : "+f"(c[0]), "+f"(c[1]), "+f"(c[2]), "+f"(c[3])
        : "r"(a[0]), "r"(a[1]), "r"(a[2]), "r"(a[3]), "r"(b0), "r"(b1));
}
__device__ __forceinline__ void ldsm4(unsigned r[4], uint32_t addr) {
    asm volatile("ldmatrix.sync.aligned.m8n8.x4.shared.b16 {%0,%1,%2,%3}, [%4];"
                 : "=r"(r[0]), "=r"(r[1]), "=r"(r[2]), "=r"(r[3]) : "r"(addr));
}
__device__ __forceinline__ void ldsm4t(unsigned r[4], uint32_t addr) {
    asm volatile("ldmatrix.sync.aligned.m8n8.x4.trans.shared.b16 {%0,%1,%2,%3}, [%4];"
                 : "=r"(r[0]), "=r"(r[1]), "=r"(r[2]), "=r"(r[3]) : "r"(addr));
}
__device__ __forceinline__ unsigned h2u(float a, float b) {
    __half2 h = __floats2half2_rn(a, b);
    return *(unsigned*)&h;
}
__device__ __forceinline__ unsigned ex2h2(unsigned x) {
    unsigned r;
    asm("ex2.approx.f16x2 %0, %1;" : "=r"(r) : "r"(x));
    return r;
}

// ---------------------------------------------------------------------------
// Pre-pass kernels
// ---------------------------------------------------------------------------
__global__ __launch_bounds__(256)
void f2h_k(const float* __restrict__ src, __half* __restrict__ dst)
{
    int i = blockIdx.x * 256 + threadIdx.x;     // handles 8 floats
    float4 a = ((const float4*)src)[2 * i];
    float4 b = ((const float4*)src)[2 * i + 1];
    uint4 o;
    o.x = h2u(a.x, a.y); o.y = h2u(a.z, a.w);
    o.z = h2u(b.x, b.y); o.w = h2u(b.z, b.w);
    ((uint4*)dst)[i] = o;
}

// transpose + fp16: src[R][C] f32 -> dst[C][R] fp16
__global__ __launch_bounds__(256)
void transpose_h(const float* __restrict__ src, __half* __restrict__ dst,
                 int R, int C)
{
    __shared__ float tile[32][33];
    const int bx = blockIdx.x * 32;
    const int by = blockIdx.y * 32;
    const int tx = threadIdx.x & 31;
    const int ty = threadIdx.x >> 5;
#pragma unroll
    for (int i = 0; i < 32; i += 8)
        tile[ty + i][tx] = src[(size_t)(by + ty + i) * C + bx + tx];
    __syncthreads();
#pragma unroll
    for (int i = 0; i < 32; i += 8)
        dst[(size_t)(bx + ty + i) * R + by + tx] = __float2half(tile[tx][ty + i]);
}

// ---------------------------------------------------------------------------
// fp16 tensor-core GEMM: C[M,N] = A[M,1024] @ Bt[N,1024]^T + bias
// CTA tile 128x256, BK=64 per stage, 3-stage cp.async, one barrier per slab.
// 8 warps (2M x 4N), warp tile 64x64: 8 ldsm -> 32 mma per k16 step
// (smem reads per mma cut to 2/3 vs 64x32 warp tile; writes per mma x0.75).
// MODE 0: fp32 store.  MODE 1: QKV scatter -> fp16 [B,H,T,Dh],
//         Q scaled by 0.125*log2(e) (exp2-domain softmax downstream).
// ---------------------------------------------------------------------------
#define LSTR 36                          // words per row: 32 data + 4 pad
#define AT_ROWS 128
#define BT_ROWS 256
#define STG_WORDS ((AT_ROWS+BT_ROWS)*LSTR)   // 13824 words
#define PIPE 3
#define NSLAB 16                         // 1024 / 64
#define GEMM_SMEM (PIPE*STG_WORDS*4)     // 165888 B

#define QSCALE 0.18033688f               // 0.125 * log2(e)

template<int N, int MODE>
__global__ __launch_bounds__(256, 1)
void gemm16(const __half* __restrict__ A, const __half* __restrict__ Bt,
            const float* __restrict__ bias,
            void* __restrict__ O0, void* __restrict__ O1, void* __restrict__ O2)
{
    extern __shared__ uint32_t sw[];
    const int tid  = threadIdx.x;
    const int w    = tid >> 5;
    const int lane = tid & 31;
    const int g    = lane >> 2;
    const int t    = lane & 3;
    const int wm   = (w & 1) * 64;       // 2 M-groups
    const int wn   = (w >> 1) * 64;      // 4 N-groups
    const int bm   = blockIdx.y * 128;
    const int bn   = blockIdx.x * 256;
    const uint32_t smem_base = smem_u32(sw);

    const int l7        = lane & 7;
    const int a_row_off = l7 + ((lane & 8) ? 8 : 0);
    const int a_col4    = ((lane >> 4) & 1) * 4;
    const int sel       = lane >> 3;
    const int b_row_off = l7 + ((sel & 2) ? 8 : 0);
    const int b_col4    = (sel & 1) * 4;

    // cooperative load: 384 rows x 8 chunks = 3072 cp16, 12 per thread
    auto issue = [&](int slab, int st) {
        const int k0 = slab * 64;
        const uint32_t base = smem_base + (uint32_t)st * STG_WORDS * 4;
#pragma unroll
        for (int r = 0; r < 12; r++) {
            const int i   = tid + r * 256;
            const int row = i >> 3;          // 0..383
            const int c   = i & 7;
            const uint32_t saddr = base + (row * LSTR + c * 4) * 4;
            if (row < AT_ROWS)
                cp16(saddr, &A[(size_t)(bm + row) * 1024 + k0 + c * 8]);
            else
                cp16(saddr, &Bt[(size_t)(bn + row - AT_ROWS) * 1024 + k0 + c * 8]);
        }
        CP_COMMIT();
    };

    issue(0, 0); issue(1, 1);            // PIPE-1 outstanding

    float acc[4][8][4];
#pragma unroll
    for (int mi = 0; mi < 4; mi++)
#pragma unroll
        for (int ni = 0; ni < 8; ni++)
#pragma unroll
            for (int c = 0; c < 4; c++) acc[mi][ni][c] = 0.f;

    for (int s = 0; s < NSLAB; s++) {
        CP_WAIT(PIPE - 2);               // slab s resident
        __syncthreads();                 // all warps done with slab s-1's slot
        if (s + PIPE - 1 < NSLAB) issue(s + PIPE - 1, (s + PIPE - 1) % PIPE);
        const uint32_t As_b = smem_base + (uint32_t)(s % PIPE) * STG_WORDS * 4;
        const uint32_t Bs_b = As_b + AT_ROWS * LSTR * 4;
#pragma unroll
        for (int kk = 0; kk < 4; kk++) {
            unsigned a[4][4];
#pragma unroll
            for (int mi = 0; mi < 4; mi++)
                ldsm4(a[mi], As_b + (((wm + mi * 16) + a_row_off) * LSTR
                                     + a_col4 + kk * 8) * 4);
            unsigned b[4][4];
#pragma unroll
            for (int nip = 0; nip < 4; nip++)
                ldsm4(b[nip], Bs_b + (((wn + nip * 16) + b_row_off) * LSTR
                                      + b_col4 + kk * 8) * 4);
#pragma unroll
            for (int nip = 0; nip < 4; nip++)
#pragma unroll
                for (int mi = 0; mi < 4; mi++) {
                    mma_f16(acc[mi][2 * nip],     a[mi], b[nip][0], b[nip][1]);
                    mma_f16(acc[mi][2 * nip + 1], a[mi], b[nip][2], b[nip][3]);
                }
        }
    }

    // epilogue
#pragma unroll
    for (int mi = 0; mi < 4; mi++) {
#pragma unroll
        for (int ni = 0; ni < 8; ni++) {
            const int r0 = bm + wm + mi * 16 + g;
            const int c0 = bn + wn + ni * 8 + 2 * t;
            const float b0 = bias[c0], b1 = bias[c0 + 1];
            float v00 = acc[mi][ni][0] + b0, v01 = acc[mi][ni][1] + b1;
            float v10 = acc[mi][ni][2] + b0, v11 = acc[mi][ni][3] + b1;
            if (MODE == 0) {
                float* O = (float*)O0;
                *(float2*)&O[(size_t)r0 * N + c0]       = make_float2(v00, v01);
                *(float2*)&O[(size_t)(r0 + 8) * N + c0] = make_float2(v10, v11);
            } else {
                const int sec = c0 >> 10;          // 0=q,1=k,2=v
                const int cc  = c0 & 1023;
                const int h   = cc >> 6;
                const int d   = cc & 63;
                __half* dst = (sec == 0) ? (__half*)O0
                            : (sec == 1) ? (__half*)O1 : (__half*)O2;
                const float sc = (sec == 0) ? QSCALE : 1.0f;
                {
                    const int m = r0;
                    const size_t o = (((size_t)((m >> 11) * HH + h)) * TT + (m & 2047)) * DHD + d;
                    *(unsigned*)&dst[o] = h2u(v00 * sc, v01 * sc);
                }
                {
                    const int m = r0 + 8;
                    const size_t o = (((size_t)((m >> 11) * HH + h)) * TT + (m & 2047)) * DHD + d;
                    *(unsigned*)&dst[o] = h2u(v10 * sc, v11 * sc);
                }
            }
        }
    }
}

// ---------------------------------------------------------------------------
// Causal flash attention, fp16 mma m16n8k16, exp2-domain softmax with
// ex2.approx.f16x2 (p computed directly as fp16 pairs = PV A-fragments).
// K/V double-buffered via cp.async; V via ldmatrix.x4.trans.
// Block = 128 queries of one (b,h). 256 threads = 8 warps x 16 rows.
// ---------------------------------------------------------------------------
#define AST 36
#define KV_TILE_WORDS (64*AST)
#define ATT_WORDS (128*AST + 4*KV_TILE_WORDS)   // Q + 2 stages x (K,V)
#define ATT_SMEM_BYTES (ATT_WORDS * 4)

__global__ __launch_bounds__(256)
void attn16(__half* __restrict__ O)
{
    extern __shared__ uint32_t sm[];
    uint32_t* Qs = sm;                           // [128][36]

    const int tid  = threadIdx.x;
    const int w    = tid >> 5;
    const int lane = tid & 31;
    const int g    = lane >> 2;
    const int t    = lane & 3;
    const int bh   = blockIdx.y;                 // 0..63
    const int qt   = (gridDim.x - 1) - blockIdx.x;   // heavy tiles first
    const int b    = bh >> 4;
    const int h    = bh & 15;
    const size_t base = (size_t)bh * TT * DHD;
    const int q0   = qt * 128;
    const int rw   = w * 16;

    const uint32_t qs_byte  = smem_u32(sm);
    const uint32_t kv0_byte = qs_byte + 128 * AST * 4;   // stage0 K

    const int l7        = lane & 7;
    const int a_row_off = l7 + ((lane & 8) ? 8 : 0);
    const int a_col4    = ((lane >> 4) & 1) * 4;
    const int sel       = lane >> 3;
    const int b_row_off = l7 + ((sel & 2) ? 8 : 0);
    const int b_col4    = (sel & 1) * 4;
    const int v_row_off = l7 + ((sel & 1) ? 8 : 0);
    const int v_col_b   = (sel >> 1) * 16;

    const int krow = tid >> 2;                   // 0..63
    const int kc0  = (tid & 3) * 2;

    auto issue_kv = [&](int kt, int st) {
        const uint32_t kb = kv0_byte + (uint32_t)st * 2 * KV_TILE_WORDS * 4;
        const uint32_t vb = kb + KV_TILE_WORDS * 4;
        const size_t go = base + (size_t)(kt * 64 + krow) * DHD;
        cp16(kb + (krow * AST + kc0 * 4) * 4,       &g_K16[go + kc0 * 8]);
        cp16(kb + (krow * AST + (kc0 + 1) * 4) * 4, &g_K16[go + (kc0 + 1) * 8]);
        cp16(vb + (krow * AST + kc0 * 4) * 4,       &g_V16[go + kc0 * 8]);
        cp16(vb + (krow * AST + (kc0 + 1) * 4) * 4, &g_V16[go + (kc0 + 1) * 8]);
        CP_COMMIT();
    };

    issue_kv(0, 0);

    // Load Q tile (scaled by 0.125*log2e in GEMM epilogue)
#pragma unroll
    for (int it = 0; it < 4; it++) {
        const int i   = tid + it * 256;
        const int row = i >> 3;
        const int c   = i & 7;
        *(uint4*)&Qs[row * AST + c * 4] =
            *(const uint4*)&g_Q16[base + (size_t)(q0 + row) * DHD + c * 8];
    }

    float m0 = -INFINITY, m1 = -INFINITY, l0 = 0.f, l1 = 0.f;
    float oacc[8][4];
#pragma unroll
    for (int j = 0; j < 8; j++)
#pragma unroll
        for (int c = 0; c < 4; c++) oacc[j][c] = 0.f;

    const int ktmax = 2 * qt + 1;
    for (int kt = 0; kt <= ktmax; kt++) {
        const int k0g = kt * 64;
        CP_WAIT(0);
        __syncthreads();
        if (kt < ktmax) issue_kv(kt + 1, (kt + 1) & 1);

        const uint32_t ks_byte = kv0_byte + (uint32_t)(kt & 1) * 2 * KV_TILE_WORDS * 4;
        const uint32_t vs_byte = ks_byte + KV_TILE_WORDS * 4;

        // ---- S = Q K^T (log2-domain; Q pre-scaled) ----
        float sacc[8][4];
#pragma unroll
        for (int j = 0; j < 8; j++)
#pragma unroll
            for (int c = 0; c < 4; c++) sacc[j][c] = 0.f;

#pragma unroll
        for (int kk = 0; kk < 4; kk++) {
            unsigned a[4];
            ldsm4(a, qs_byte + ((rw + a_row_off) * AST + a_col4 + kk * 8) * 4);
#pragma unroll
            for (int jp = 0; jp < 4; jp++) {
                unsigned bb[4];
                ldsm4(bb, ks_byte + ((jp * 16 + b_row_off) * AST
                                     + b_col4 + kk * 8) * 4);
                mma_f16(sacc[2 * jp],     a, bb[0], bb[1]);
                mma_f16(sacc[2 * jp + 1], a, bb[2], bb[3]);
            }
        }

        // ---- causal mask ----
        if (k0g + 63 > q0 + rw) {
            const int gr0 = q0 + rw + g, gr1 = gr0 + 8;
#pragma unroll
            for (int j = 0; j < 8; j++) {
                const int gc = k0g + j * 8 + 2 * t;
                if (gc     > gr0) sacc[j][0] = -INFINITY;
                if (gc + 1 > gr0) sacc[j][1] = -INFINITY;
                if (gc     > gr1) sacc[j][2] = -INFINITY;
                if (gc + 1 > gr1) sacc[j][3] = -INFINITY;
            }
        }

        // ---- online softmax (exp2 domain; rows rw+g, rw+g+8) ----
        float mt0 = -INFINITY, mt1 = -INFINITY;
#pragma unroll
        for (int j = 0; j < 8; j++) {
            mt0 = fmaxf(mt0, fmaxf(sacc[j][0], sacc[j][1]));
            mt1 = fmaxf(mt1, fmaxf(sacc[j][2], sacc[j][3]));
        }
        mt0 = fmaxf(mt0, __shfl_xor_sync(0xffffffffu, mt0, 1));
        mt0 = fmaxf(mt0, __shfl_xor_sync(0xffffffffu, mt0, 2));
        mt1 = fmaxf(mt1, __shfl_xor_sync(0xffffffffu, mt1, 1));
        mt1 = fmaxf(mt1, __shfl_xor_sync(0xffffffffu, mt1, 2));

        const float mn0 = fmaxf(m0, mt0), mn1 = fmaxf(m1, mt1);
        const float cor0 = exp2f(m0 - mn0), cor1 = exp2f(m1 - mn1);

        // p = 2^(s - m), computed as fp16 pairs -> directly the PV A-fragments
        unsigned pa[4][4];
        float ls0 = 0.f, ls1 = 0.f;
#pragma unroll
        for (int j = 0; j < 8; j++) {
            const unsigned p01 = ex2h2(h2u(sacc[j][0] - mn0, sacc[j][1] - mn0));
            const unsigned p23 = ex2h2(h2u(sacc[j][2] - mn1, sacc[j][3] - mn1));
            const float2 f01 = __half22float2(*(const __half2*)&p01);
            const float2 f23 = __half22float2(*(const __half2*)&p23);
            ls0 += f01.x + f01.y;
            ls1 += f23.x + f23.y;
            pa[j >> 1][(j & 1) * 2 + 0] = p01;
            pa[j >> 1][(j & 1) * 2 + 1] = p23;
        }
        ls0 += __shfl_xor_sync(0xffffffffu, ls0, 1);
        ls0 += __shfl_xor_sync(0xffffffffu, ls0, 2);
        ls1 += __shfl_xor_sync(0xffffffffu, ls1, 1);
        ls1 += __shfl_xor_sync(0xffffffffu, ls1, 2);

        l0 = l0 * cor0 + ls0;  m0 = mn0;
        l1 = l1 * cor1 + ls1;  m1 = mn1;
#pragma unroll
        for (int j = 0; j < 8; j++) {
            oacc[j][0] *= cor0; oacc[j][1] *= cor0;
            oacc[j][2] *= cor1; oacc[j][3] *= cor1;
        }

        // ---- O += P V ---- (B via ldmatrix.trans of V[key][d])
#pragma unroll
        for (int kk = 0; kk < 4; kk++) {
#pragma unroll
            for (int jp = 0; jp < 4; jp++) {
                unsigned bb[4];
                ldsm4t(bb, vs_byte + ((kk * 16 + v_row_off) * AST) * 4
                                   + jp * 32 + v_col_b);
                mma_f16(oacc[2 * jp],     pa[kk], bb[0], bb[1]);
                mma_f16(oacc[2 * jp + 1], pa[kk], bb[2], bb[3]);
            }
        }
    }

    // ---- normalize, write fp16 g_O [B,T,C] ----
    const float inv0 = 1.0f / l0, inv1 = 1.0f / l1;
    const int qrow = q0 + rw + g;
    const size_t ob0 = ((size_t)b * TT + qrow)     * CC + h * DHD;
    const size_t ob1 = ((size_t)b * TT + qrow + 8) * CC + h * DHD;
#pragma unroll
    for (int j = 0; j < 8; j++) {
        const int c = j * 8 + 2 * t;
        *(unsigned*)&O[ob0 + c] = h2u(oacc[j][0] * inv0, oacc[j][1] * inv0);
        *(unsigned*)&O[ob1 + c] = h2u(oacc[j][2] * inv1, oacc[j][3] * inv1);
    }
}

// ---------------------------------------------------------------------------
extern "C" void kernel_launch(void* const* d_in, const int* in_sizes, int n_in,
                              void* d_out, int out_size)
{
    const float* x     = (const float*)d_in[0];   // [4,2048,1024]
    const float* W_qkv = (const float*)d_in[1];   // [1024,3072]
    const float* b_qkv = (const float*)d_in[2];   // [3072]
    const float* W_out = (const float*)d_in[3];   // [1024,1024]
    const float* b_out = (const float*)d_in[4];   // [1024]
    float* out = (float*)d_out;                   // [4,2048,1024]

    void *pX, *pQ, *pK, *pV, *pO, *pWq, *pWo;
    cudaGetSymbolAddress(&pX,  g_x16);
    cudaGetSymbolAddress(&pQ,  g_Q16);
    cudaGetSymbolAddress(&pK,  g_K16);
    cudaGetSymbolAddress(&pV,  g_V16);
    cudaGetSymbolAddress(&pO,  g_O16);
    cudaGetSymbolAddress(&pWq, g_Wq16);
    cudaGetSymbolAddress(&pWo, g_Wo16);

    cudaFuncSetAttribute(attn16, cudaFuncAttributeMaxDynamicSharedMemorySize,
                         ATT_SMEM_BYTES);
    cudaFuncSetAttribute(gemm16<3072,1>,
                         cudaFuncAttributeMaxDynamicSharedMemorySize, GEMM_SMEM);
    cudaFuncSetAttribute(gemm16<1024,0>,
                         cudaFuncAttributeMaxDynamicSharedMemorySize, GEMM_SMEM);

    // 0) Pre-pass: x -> fp16, weights -> fp16 transposed [N,K]
    f2h_k<<<(MM * CC) / (256 * 8), 256>>>(x, (__half*)pX);
    transpose_h<<<dim3(3072/32, 1024/32), 256>>>(W_qkv, (__half*)pWq, 1024, 3072);
    transpose_h<<<dim3(1024/32, 1024/32), 256>>>(W_out, (__half*)pWo, 1024, 1024);

    // 1) QKV projection (fp16 mma, 128x256 CTA tile, 64x64 warp tile)
    {
        dim3 grid(3072 / 256, MM / 128);
        gemm16<3072,1><<<grid, 256, GEMM_SMEM>>>((const __half*)pX,
                                                 (const __half*)pWq, b_qkv,
                                                 pQ, pK, pV);
    }
    // 2) Causal flash attention -> g_O16 [B,T,C]
    {
        dim3 grid(TT / 128, BB * HH);
        attn16<<<grid, 256, ATT_SMEM_BYTES>>>((__half*)pO);
    }
    // 3) Output projection -> d_out (fp32)
    {
        dim3 grid(1024 / 256, MM / 128);
        gemm16<1024,0><<<grid, 256, GEMM_SMEM>>>((const __half*)pO,
                                                 (const __half*)pWo, b_out,
                                                 out, nullptr, nullptr);
    }
}

// round 15
// speedup vs baseline: 1.1188x; 1.1188x over previous
#include <cuda_runtime.h>
#include <cuda_fp16.h>
#include <math.h>
#include <stdint.h>

// Problem constants
#define BB 4
#define TT 2048
#define CC 1024
#define HH 16
#define DHD 64
#define MM (BB*TT)          // 8192 rows

// Scratch (allocation-free rule: __device__ globals)
__device__ __half g_x16[MM*CC];          // x in fp16
__device__ __half g_Q16[BB*HH*TT*DHD];   // Q [B,H,T,Dh] fp16, scaled 0.125*log2(e)
__device__ __half g_K16[BB*HH*TT*DHD];
__device__ __half g_V16[BB*HH*TT*DHD];
__device__ __half g_O16[MM*CC];          // attention out [B,T,C] fp16
__device__ __half g_Wq16[3072*1024];     // W_qkv^T [N,K] fp16
__device__ __half g_Wo16[1024*1024];     // W_out^T [N,K] fp16

// ---------------------------------------------------------------------------
// helpers
// ---------------------------------------------------------------------------
__device__ __forceinline__ uint32_t smem_u32(const void* p) {
    uint32_t a;
    asm("{ .reg .u64 t; cvta.to.shared.u64 t, %1; cvt.u32.u64 %0, t; }"
        : "=r"(a) : "l"(p));
    return a;
}
__device__ __forceinline__ void cp16(uint32_t s, const void* g) {
    asm volatile("cp.async.cg.shared.global [%0], [%1], 16;" :: "r"(s), "l"(g));
}
#define CP_COMMIT() asm volatile("cp.async.commit_group;" ::: "memory")
#define CP_WAIT(n)  asm volatile("cp.async.wait_group %0;" :: "n"(n) : "memory")

__device__ __forceinline__ void mma_f16(float c[4], const unsigned a[4],
                                        const unsigned b0, const unsigned b1) {
    asm volatile(
        "mma.sync.aligned.m16n8k16.row.col.f32.f16.f16.f32 "
        "{%0,%1,%2,%3},{%4,%5,%6,%7},{%8,%9},{%0,%1,%2,%3};"
        : "+f"(c[0]), "+f"(c[1]), "+f"(c[2]), "+f"(c[3])
        : "r"(a[0]), "r"(a[1]), "r"(a[2]), "r"(a[3]), "r"(b0), "r"(b1));
}
__device__ __forceinline__ void ldsm4(unsigned r[4], uint32_t addr) {
    asm volatile("ldmatrix.sync.aligned.m8n8.x4.shared.b16 {%0,%1,%2,%3}, [%4];"
                 : "=r"(r[0]), "=r"(r[1]), "=r"(r[2]), "=r"(r[3]) : "r"(addr));
}
__device__ __forceinline__ void ldsm4t(unsigned r[4], uint32_t addr) {
    asm volatile("ldmatrix.sync.aligned.m8n8.x4.trans.shared.b16 {%0,%1,%2,%3}, [%4];"
                 : "=r"(r[0]), "=r"(r[1]), "=r"(r[2]), "=r"(r[3]) : "r"(addr));
}
__device__ __forceinline__ unsigned h2u(float a, float b) {
    __half2 h = __floats2half2_rn(a, b);
    return *(unsigned*)&h;
}
__device__ __forceinline__ unsigned ex2h2(unsigned x) {
    unsigned r;
    asm("ex2.approx.f16x2 %0, %1;" : "=r"(r) : "r"(x));
    return r;
}

// ---------------------------------------------------------------------------
// Pre-pass kernels
// ---------------------------------------------------------------------------
__global__ __launch_bounds__(256)
void f2h_k(const float* __restrict__ src, __half* __restrict__ dst)
{
    int i = blockIdx.x * 256 + threadIdx.x;     // handles 8 floats
    float4 a = ((const float4*)src)[2 * i];
    float4 b = ((const float4*)src)[2 * i + 1];
    uint4 o;
    o.x = h2u(a.x, a.y); o.y = h2u(a.z, a.w);
    o.z = h2u(b.x, b.y); o.w = h2u(b.z, b.w);
    ((uint4*)dst)[i] = o;
}

// transpose + fp16: src[R][C] f32 -> dst[C][R] fp16
__global__ __launch_bounds__(256)
void transpose_h(const float* __restrict__ src, __half* __restrict__ dst,
                 int R, int C)
{
    __shared__ float tile[32][33];
    const int bx = blockIdx.x * 32;
    const int by = blockIdx.y * 32;
    const int tx = threadIdx.x & 31;
    const int ty = threadIdx.x >> 5;
#pragma unroll
    for (int i = 0; i < 32; i += 8)
        tile[ty + i][tx] = src[(size_t)(by + ty + i) * C + bx + tx];
    __syncthreads();
#pragma unroll
    for (int i = 0; i < 32; i += 8)
        dst[(size_t)(bx + ty + i) * R + by + tx] = __float2half(tile[tx][ty + i]);
}

// ---------------------------------------------------------------------------
// fp16 tensor-core GEMM: C[M,N] = A[M,1024] @ Bt[N,1024]^T + bias
// 128x128 tile, BK=64 per stage (4 x k16), 3-stage cp.async, one barrier
// per slab.  8 warps (2M x 4N), warp tile 64x32.
// De-bunching: odd warps traverse kk in rotated order (accumulation-order
// only); cp.async issue for slab s+2 moved after the first kk group so the
// LDGSTS burst does not collide with the post-barrier ldsm burst.
// MODE 0: fp32 store.  MODE 1: QKV scatter -> fp16 [B,H,T,Dh],
//         Q scaled by 0.125*log2(e) (exp2-domain softmax downstream).
// ---------------------------------------------------------------------------
#define LSTR 36                      // words per row: 32 data + 4 pad
#define TILE_WORDS (128*LSTR)        // 4608
#define STG_WORDS (2*TILE_WORDS)
#define PIPE 3
#define NSLAB 16                     // 1024 / 64
#define GEMM_SMEM (PIPE*STG_WORDS*4) // 110592 B

#define QSCALE 0.18033688f           // 0.125 * log2(e)

template<int N, int MODE>
__global__ __launch_bounds__(256, 2)
void gemm16(const __half* __restrict__ A, const __half* __restrict__ Bt,
            const float* __restrict__ bias,
            void* __restrict__ O0, void* __restrict__ O1, void* __restrict__ O2)
{
    extern __shared__ uint32_t sw[];
    const int tid  = threadIdx.x;
    const int w    = tid >> 5;
    const int lane = tid & 31;
    const int g    = lane >> 2;
    const int t    = lane & 3;
    const int wm   = (w >> 2) * 64;
    const int wn   = (w & 3) * 32;
    const int bm   = blockIdx.y * 128;
    const int bn   = blockIdx.x * 128;
    const uint32_t smem_base = smem_u32(sw);

    const int l7        = lane & 7;
    const int a_row_off = l7 + ((lane & 8) ? 8 : 0);
    const int a_col4    = ((lane >> 4) & 1) * 4;
    const int sel       = lane >> 3;
    const int b_row_off = l7 + ((sel & 2) ? 8 : 0);
    const int b_col4    = (sel & 1) * 4;
    const int kk_rot    = (w & 1) << 1;      // odd warps start at kk=2

    auto issue = [&](int slab, int st) {
        const int k0 = slab * 64;
        const uint32_t baseA = smem_base + (uint32_t)st * STG_WORDS * 4;
        const uint32_t baseB = baseA + TILE_WORDS * 4;
#pragma unroll
        for (int r = 0; r < 4; r++) {
            const int i   = tid + r * 256;     // chunk index, 1024 per tile
            const int row = i >> 3;
            const int c   = i & 7;
            cp16(baseA + (row * LSTR + c * 4) * 4,
                 &A[(size_t)(bm + row) * 1024 + k0 + c * 8]);
            cp16(baseB + (row * LSTR + c * 4) * 4,
                 &Bt[(size_t)(bn + row) * 1024 + k0 + c * 8]);
        }
        CP_COMMIT();
    };

    issue(0, 0); issue(1, 1);        // PIPE-1 outstanding

    float acc[4][4][4];
#pragma unroll
    for (int mi = 0; mi < 4; mi++)
#pragma unroll
        for (int ni = 0; ni < 4; ni++)
#pragma unroll
            for (int c = 0; c < 4; c++) acc[mi][ni][c] = 0.f;

    for (int s = 0; s < NSLAB; s++) {
        CP_WAIT(PIPE - 2);           // slab s resident
        __syncthreads();             // all warps done with slab s-1's slot
        const uint32_t As_b = smem_base + (uint32_t)(s % PIPE) * STG_WORDS * 4;
        const uint32_t Bs_b = As_b + TILE_WORDS * 4;
#pragma unroll
        for (int kki = 0; kki < 4; kki++) {
            const int kk = (kki + kk_rot) & 3;
            unsigned a[4][4];
#pragma unroll
            for (int mi = 0; mi < 4; mi++)
                ldsm4(a[mi], As_b + (((wm + mi * 16) + a_row_off) * LSTR
                                     + a_col4 + kk * 8) * 4);
            unsigned b[2][4];
#pragma unroll
            for (int nip = 0; nip < 2; nip++)
                ldsm4(b[nip], Bs_b + (((wn + nip * 16) + b_row_off) * LSTR
                                      + b_col4 + kk * 8) * 4);
#pragma unroll
            for (int nip = 0; nip < 2; nip++)
#pragma unroll
                for (int mi = 0; mi < 4; mi++) {
                    mma_f16(acc[mi][2 * nip],     a[mi], b[nip][0], b[nip][1]);
                    mma_f16(acc[mi][2 * nip + 1], a[mi], b[nip][2], b[nip][3]);
                }
            if (kki == 0 && s + PIPE - 1 < NSLAB)
                issue(s + PIPE - 1, (s + PIPE - 1) % PIPE);
        }
    }

    // epilogue
#pragma unroll
    for (int mi = 0; mi < 4; mi++) {
#pragma unroll
        for (int ni = 0; ni < 4; ni++) {
            const int r0 = bm + wm + mi * 16 + g;
            const int c0 = bn + wn + ni * 8 + 2 * t;
            const float b0 = bias[c0], b1 = bias[c0 + 1];
            float v00 = acc[mi][ni][0] + b0, v01 = acc[mi][ni][1] + b1;
            float v10 = acc[mi][ni][2] + b0, v11 = acc[mi][ni][3] + b1;
            if (MODE == 0) {
                float* O = (float*)O0;
                *(float2*)&O[(size_t)r0 * N + c0]       = make_float2(v00, v01);
                *(float2*)&O[(size_t)(r0 + 8) * N + c0] = make_float2(v10, v11);
            } else {
                const int sec = c0 >> 10;          // 0=q,1=k,2=v
                const int cc  = c0 & 1023;
                const int h   = cc >> 6;
                const int d   = cc & 63;
                __half* dst = (sec == 0) ? (__half*)O0
                            : (sec == 1) ? (__half*)O1 : (__half*)O2;
                const float sc = (sec == 0) ? QSCALE : 1.0f;
                {
                    const int m = r0;
                    const size_t o = (((size_t)((m >> 11) * HH + h)) * TT + (m & 2047)) * DHD + d;
                    *(unsigned*)&dst[o] = h2u(v00 * sc, v01 * sc);
                }
                {
                    const int m = r0 + 8;
                    const size_t o = (((size_t)((m >> 11) * HH + h)) * TT + (m & 2047)) * DHD + d;
                    *(unsigned*)&dst[o] = h2u(v10 * sc, v11 * sc);
                }
            }
        }
    }
}

// ---------------------------------------------------------------------------
// Causal flash attention, fp16 mma m16n8k16, exp2-domain softmax with
// ex2.approx.f16x2 (p computed directly as fp16 pairs = PV A-fragments).
// K/V double-buffered via cp.async; V via ldmatrix.x4.trans.
// Causal warp-skip: warps whose 16 query rows are entirely below the key
// tile skip all math (identity on m/l/O) but still run barriers/cp.async.
// Block = 128 queries of one (b,h). 256 threads = 8 warps x 16 rows.
// ---------------------------------------------------------------------------
#define AST 36
#define KV_TILE_WORDS (64*AST)
#define ATT_WORDS (128*AST + 4*KV_TILE_WORDS)   // Q + 2 stages x (K,V)
#define ATT_SMEM_BYTES (ATT_WORDS * 4)

__global__ __launch_bounds__(256, 2)
void attn16(__half* __restrict__ O)
{
    extern __shared__ uint32_t sm[];
    uint32_t* Qs = sm;                           // [128][36]

    const int tid  = threadIdx.x;
    const int w    = tid >> 5;
    const int lane = tid & 31;
    const int g    = lane >> 2;
    const int t    = lane & 3;
    const int bh   = blockIdx.y;                 // 0..63
    const int qt   = (gridDim.x - 1) - blockIdx.x;   // heavy tiles first
    const int b    = bh >> 4;
    const int h    = bh & 15;
    const size_t base = (size_t)bh * TT * DHD;
    const int q0   = qt * 128;
    const int rw   = w * 16;

    const uint32_t qs_byte  = smem_u32(sm);
    const uint32_t kv0_byte = qs_byte + 128 * AST * 4;   // stage0 K

    const int l7        = lane & 7;
    const int a_row_off = l7 + ((lane & 8) ? 8 : 0);
    const int a_col4    = ((lane >> 4) & 1) * 4;
    const int sel       = lane >> 3;
    const int b_row_off = l7 + ((sel & 2) ? 8 : 0);
    const int b_col4    = (sel & 1) * 4;
    const int v_row_off = l7 + ((sel & 1) ? 8 : 0);
    const int v_col_b   = (sel >> 1) * 16;

    const int krow = tid >> 2;                   // 0..63
    const int kc0  = (tid & 3) * 2;

    auto issue_kv = [&](int kt, int st) {
        const uint32_t kb = kv0_byte + (uint32_t)st * 2 * KV_TILE_WORDS * 4;
        const uint32_t vb = kb + KV_TILE_WORDS * 4;
        const size_t go = base + (size_t)(kt * 64 + krow) * DHD;
        cp16(kb + (krow * AST + kc0 * 4) * 4,       &g_K16[go + kc0 * 8]);
        cp16(kb + (krow * AST + (kc0 + 1) * 4) * 4, &g_K16[go + (kc0 + 1) * 8]);
        cp16(vb + (krow * AST + kc0 * 4) * 4,       &g_V16[go + kc0 * 8]);
        cp16(vb + (krow * AST + (kc0 + 1) * 4) * 4, &g_V16[go + (kc0 + 1) * 8]);
        CP_COMMIT();
    };

    issue_kv(0, 0);

    // Load Q tile (scaled by 0.125*log2e in GEMM epilogue)
#pragma unroll
    for (int it = 0; it < 4; it++) {
        const int i   = tid + it * 256;
        const int row = i >> 3;
        const int c   = i & 7;
        *(uint4*)&Qs[row * AST + c * 4] =
            *(const uint4*)&g_Q16[base + (size_t)(q0 + row) * DHD + c * 8];
    }

    float m0 = -INFINITY, m1 = -INFINITY, l0 = 0.f, l1 = 0.f;
    float oacc[8][4];
#pragma unroll
    for (int j = 0; j < 8; j++)
#pragma unroll
        for (int c = 0; c < 4; c++) oacc[j][c] = 0.f;

    const int ktmax = 2 * qt + 1;
    for (int kt = 0; kt <= ktmax; kt++) {
        const int k0g = kt * 64;
        CP_WAIT(0);
        __syncthreads();
        if (kt < ktmax) issue_kv(kt + 1, (kt + 1) & 1);

        // causal warp-skip: this warp's rows all precede the key tile?
        if (k0g > q0 + rw + 15) continue;

        const uint32_t ks_byte = kv0_byte + (uint32_t)(kt & 1) * 2 * KV_TILE_WORDS * 4;
        const uint32_t vs_byte = ks_byte + KV_TILE_WORDS * 4;

        // ---- S = Q K^T (log2-domain; Q pre-scaled) ----
        float sacc[8][4];
#pragma unroll
        for (int j = 0; j < 8; j++)
#pragma unroll
            for (int c = 0; c < 4; c++) sacc[j][c] = 0.f;

#pragma unroll
        for (int kk = 0; kk < 4; kk++) {
            unsigned a[4];
            ldsm4(a, qs_byte + ((rw + a_row_off) * AST + a_col4 + kk * 8) * 4);
#pragma unroll
            for (int jp = 0; jp < 4; jp++) {
                unsigned bb[4];
                ldsm4(bb, ks_byte + ((jp * 16 + b_row_off) * AST
                                     + b_col4 + kk * 8) * 4);
                mma_f16(sacc[2 * jp],     a, bb[0], bb[1]);
                mma_f16(sacc[2 * jp + 1], a, bb[2], bb[3]);
            }
        }

        // ---- causal mask ----
        if (k0g + 63 > q0 + rw) {
            const int gr0 = q0 + rw + g, gr1 = gr0 + 8;
#pragma unroll
            for (int j = 0; j < 8; j++) {
                const int gc = k0g + j * 8 + 2 * t;
                if (gc     > gr0) sacc[j][0] = -INFINITY;
                if (gc + 1 > gr0) sacc[j][1] = -INFINITY;
                if (gc     > gr1) sacc[j][2] = -INFINITY;
                if (gc + 1 > gr1) sacc[j][3] = -INFINITY;
            }
        }

        // ---- online softmax (exp2 domain; rows rw+g, rw+g+8) ----
        float mt0 = -INFINITY, mt1 = -INFINITY;
#pragma unroll
        for (int j = 0; j < 8; j++) {
            mt0 = fmaxf(mt0, fmaxf(sacc[j][0], sacc[j][1]));
            mt1 = fmaxf(mt1, fmaxf(sacc[j][2], sacc[j][3]));
        }
        // packed half2 max reduction across the 4 lanes of each row
        {
            unsigned mp = h2u(mt0, mt1);
            unsigned o1 = __shfl_xor_sync(0xffffffffu, mp, 1);
            __half2 hm = __hmax2(*(__half2*)&mp, *(__half2*)&o1);
            unsigned m2u = *(unsigned*)&hm;
            unsigned o2 = __shfl_xor_sync(0xffffffffu, m2u, 2);
            hm = __hmax2(*(__half2*)&m2u, *(__half2*)&o2);
            const float2 mf = __half22float2(hm);
            mt0 = mf.x; mt1 = mf.y;
        }

        const float mn0 = fmaxf(m0, mt0), mn1 = fmaxf(m1, mt1);
        const float cor0 = exp2f(m0 - mn0), cor1 = exp2f(m1 - mn1);

        // p = 2^(s - m), computed as fp16 pairs -> directly the PV A-fragments
        unsigned pa[4][4];
        float ls0 = 0.f, ls1 = 0.f;
#pragma unroll
        for (int j = 0; j < 8; j++) {
            const unsigned p01 = ex2h2(h2u(sacc[j][0] - mn0, sacc[j][1] - mn0));
            const unsigned p23 = ex2h2(h2u(sacc[j][2] - mn1, sacc[j][3] - mn1));
            const float2 f01 = __half22float2(*(const __half2*)&p01);
            const float2 f23 = __half22float2(*(const __half2*)&p23);
            ls0 += f01.x + f01.y;
            ls1 += f23.x + f23.y;
            pa[j >> 1][(j & 1) * 2 + 0] = p01;
            pa[j >> 1][(j & 1) * 2 + 1] = p23;
        }
        ls0 += __shfl_xor_sync(0xffffffffu, ls0, 1);
        ls0 += __shfl_xor_sync(0xffffffffu, ls0, 2);
        ls1 += __shfl_xor_sync(0xffffffffu, ls1, 1);
        ls1 += __shfl_xor_sync(0xffffffffu, ls1, 2);

        l0 = l0 * cor0 + ls0;  m0 = mn0;
        l1 = l1 * cor1 + ls1;  m1 = mn1;
#pragma unroll
        for (int j = 0; j < 8; j++) {
            oacc[j][0] *= cor0; oacc[j][1] *= cor0;
            oacc[j][2] *= cor1; oacc[j][3] *= cor1;
        }

        // ---- O += P V ---- (B via ldmatrix.trans of V[key][d])
#pragma unroll
        for (int kk = 0; kk < 4; kk++) {
#pragma unroll
            for (int jp = 0; jp < 4; jp++) {
                unsigned bb[4];
                ldsm4t(bb, vs_byte + ((kk * 16 + v_row_off) * AST) * 4
                                   + jp * 32 + v_col_b);
                mma_f16(oacc[2 * jp],     pa[kk], bb[0], bb[1]);
                mma_f16(oacc[2 * jp + 1], pa[kk], bb[2], bb[3]);
            }
        }
    }

    // ---- normalize, write fp16 g_O [B,T,C] ----
    const float inv0 = 1.0f / l0, inv1 = 1.0f / l1;
    const int qrow = q0 + rw + g;
    const size_t ob0 = ((size_t)b * TT + qrow)     * CC + h * DHD;
    const size_t ob1 = ((size_t)b * TT + qrow + 8) * CC + h * DHD;
#pragma unroll
    for (int j = 0; j < 8; j++) {
        const int c = j * 8 + 2 * t;
        *(unsigned*)&O[ob0 + c] = h2u(oacc[j][0] * inv0, oacc[j][1] * inv0);
        *(unsigned*)&O[ob1 + c] = h2u(oacc[j][2] * inv1, oacc[j][3] * inv1);
    }
}

// ---------------------------------------------------------------------------
extern "C" void kernel_launch(void* const* d_in, const int* in_sizes, int n_in,
                              void* d_out, int out_size)
{
    const float* x     = (const float*)d_in[0];   // [4,2048,1024]
    const float* W_qkv = (const float*)d_in[1];   // [1024,3072]
    const float* b_qkv = (const float*)d_in[2];   // [3072]
    const float* W_out = (const float*)d_in[3];   // [1024,1024]
    const float* b_out = (const float*)d_in[4];   // [1024]
    float* out = (float*)d_out;                   // [4,2048,1024]

    void *pX, *pQ, *pK, *pV, *pO, *pWq, *pWo;
    cudaGetSymbolAddress(&pX,  g_x16);
    cudaGetSymbolAddress(&pQ,  g_Q16);
    cudaGetSymbolAddress(&pK,  g_K16);
    cudaGetSymbolAddress(&pV,  g_V16);
    cudaGetSymbolAddress(&pO,  g_O16);
    cudaGetSymbolAddress(&pWq, g_Wq16);
    cudaGetSymbolAddress(&pWo, g_Wo16);

    cudaFuncSetAttribute(attn16, cudaFuncAttributeMaxDynamicSharedMemorySize,
                         ATT_SMEM_BYTES);
    cudaFuncSetAttribute(gemm16<3072,1>,
                         cudaFuncAttributeMaxDynamicSharedMemorySize, GEMM_SMEM);
    cudaFuncSetAttribute(gemm16<1024,0>,
                         cudaFuncAttributeMaxDynamicSharedMemorySize, GEMM_SMEM);

    // 0) Pre-pass: x -> fp16, weights -> fp16 transposed [N,K]
    f2h_k<<<(MM * CC) / (256 * 8), 256>>>(x, (__half*)pX);
    transpose_h<<<dim3(3072/32, 1024/32), 256>>>(W_qkv, (__half*)pWq, 1024, 3072);
    transpose_h<<<dim3(1024/32, 1024/32), 256>>>(W_out, (__half*)pWo, 1024, 1024);

    // 1) QKV projection (fp16 mma, 128x128 CTA tile, 64x32 warp tile)
    {
        dim3 grid(3072 / 128, MM / 128);
        gemm16<3072,1><<<grid, 256, GEMM_SMEM>>>((const __half*)pX,
                                                 (const __half*)pWq, b_qkv,
                                                 pQ, pK, pV);
    }
    // 2) Causal flash attention -> g_O16 [B,T,C]
    {
        dim3 grid(TT / 128, BB * HH);
        attn16<<<grid, 256, ATT_SMEM_BYTES>>>((__half*)pO);
    }
    // 3) Output projection -> d_out (fp32)
    {
        dim3 grid(1024 / 128, MM / 128);
        gemm16<1024,0><<<grid, 256, GEMM_SMEM>>>((const __half*)pO,
                                                 (const __half*)pWo, b_out,
                                                 out, nullptr, nullptr);
    }
}

// round 16
// speedup vs baseline: 1.1384x; 1.0175x over previous
#include <cuda_runtime.h>
#include <cuda_fp16.h>
#include <math.h>
#include <stdint.h>

// Problem constants
#define BB 4
#define TT 2048
#define CC 1024
#define HH 16
#define DHD 64
#define MM (BB*TT)          // 8192 rows

// Scratch (allocation-free rule: __device__ globals)
__device__ __half g_x16[MM*CC];          // x in fp16
__device__ __half g_Q16[BB*HH*TT*DHD];   // Q [B,H,T,Dh] fp16, scaled 0.125*log2(e)
__device__ __half g_K16[BB*HH*TT*DHD];
__device__ __half g_V16[BB*HH*TT*DHD];
__device__ __half g_O16[MM*CC];          // attention out [B,T,C] fp16
__device__ __half g_Wq16[3072*1024];     // W_qkv^T [N,K] fp16
__device__ __half g_Wo16[1024*1024];     // W_out^T [N,K] fp16

// ---------------------------------------------------------------------------
// helpers
// ---------------------------------------------------------------------------
__device__ __forceinline__ uint32_t smem_u32(const void* p) {
    uint32_t a;
    asm("{ .reg .u64 t; cvta.to.shared.u64 t, %1; cvt.u32.u64 %0, t; }"
        : "=r"(a) : "l"(p));
    return a;
}
__device__ __forceinline__ void cp16(uint32_t s, const void* g) {
    asm volatile("cp.async.cg.shared.global [%0], [%1], 16;" :: "r"(s), "l"(g));
}
#define CP_COMMIT() asm volatile("cp.async.commit_group;" ::: "memory")
#define CP_WAIT(n)  asm volatile("cp.async.wait_group %0;" :: "n"(n) : "memory")

__device__ __forceinline__ void mma_f16(float c[4], const unsigned a[4],
                                        const unsigned b0, const unsigned b1) {
    asm volatile(
        "mma.sync.aligned.m16n8k16.row.col.f32.f16.f16.f32 "
        "{%0,%1,%2,%3},{%4,%5,%6,%7},{%8,%9},{%0,%1,%2,%3};"
        : "+f"(c[0]), "+f"(c[1]), "+f"(c[2]), "+f"(c[3])
        : "r"(a[0]), "r"(a[1]), "r"(a[2]), "r"(a[3]), "r"(b0), "r"(b1));
}
__device__ __forceinline__ void ldsm4(unsigned r[4], uint32_t addr) {
    asm volatile("ldmatrix.sync.aligned.m8n8.x4.shared.b16 {%0,%1,%2,%3}, [%4];"
                 : "=r"(r[0]), "=r"(r[1]), "=r"(r[2]), "=r"(r[3]) : "r"(addr));
}
__device__ __forceinline__ void ldsm4t(unsigned r[4], uint32_t addr) {
    asm volatile("ldmatrix.sync.aligned.m8n8.x4.trans.shared.b16 {%0,%1,%2,%3}, [%4];"
                 : "=r"(r[0]), "=r"(r[1]), "=r"(r[2]), "=r"(r[3]) : "r"(addr));
}
__device__ __forceinline__ unsigned h2u(float a, float b) {
    __half2 h = __floats2half2_rn(a, b);
    return *(unsigned*)&h;
}
__device__ __forceinline__ unsigned ex2h2(unsigned x) {
    unsigned r;
    asm("ex2.approx.f16x2 %0, %1;" : "=r"(r) : "r"(x));
    return r;
}

// ---------------------------------------------------------------------------
// Pre-pass kernels
// ---------------------------------------------------------------------------
__global__ __launch_bounds__(256)
void f2h_k(const float* __restrict__ src, __half* __restrict__ dst)
{
    int i = blockIdx.x * 256 + threadIdx.x;     // handles 8 floats
    float4 a = ((const float4*)src)[2 * i];
    float4 b = ((const float4*)src)[2 * i + 1];
    uint4 o;
    o.x = h2u(a.x, a.y); o.y = h2u(a.z, a.w);
    o.z = h2u(b.x, b.y); o.w = h2u(b.z, b.w);
    ((uint4*)dst)[i] = o;
}

// transpose + fp16: src[R][C] f32 -> dst[C][R] fp16
__global__ __launch_bounds__(256)
void transpose_h(const float* __restrict__ src, __half* __restrict__ dst,
                 int R, int C)
{
    __shared__ float tile[32][33];
    const int bx = blockIdx.x * 32;
    const int by = blockIdx.y * 32;
    const int tx = threadIdx.x & 31;
    const int ty = threadIdx.x >> 5;
#pragma unroll
    for (int i = 0; i < 32; i += 8)
        tile[ty + i][tx] = src[(size_t)(by + ty + i) * C + bx + tx];
    __syncthreads();
#pragma unroll
    for (int i = 0; i < 32; i += 8)
        dst[(size_t)(bx + ty + i) * R + by + tx] = __float2half(tile[tx][ty + i]);
}

// ---------------------------------------------------------------------------
// Persistent fp16 tensor-core GEMM: C[M,N] = A[M,1024] @ Bt[N,1024]^T + bias
// Fixed grid of GPERS CTAs; each owns tiles bid, bid+GPERS, ... and runs ONE
// continuous slab loop over (tile, slab) pairs -- the 3-stage cp.async
// pipeline never drains across tile boundaries.  128x128 tile, BK=64/stage,
// one barrier per slab, 8 warps (2M x 4N), warp tile 64x32, ldmatrix.x4.
// Epilogue is reg->global (no smem, no barrier), runs between slab barriers.
// MODE 0: fp32 store.  MODE 1: QKV scatter -> fp16 [B,H,T,Dh],
//         Q scaled by 0.125*log2(e) (exp2-domain softmax downstream).
// ---------------------------------------------------------------------------
#define LSTR 36                      // words per row: 32 data + 4 pad
#define TILE_WORDS (128*LSTR)        // 4608
#define STG_WORDS (2*TILE_WORDS)
#define PIPE 3
#define GEMM_SMEM (PIPE*STG_WORDS*4) // 110592 B
#define GPERS 296                    // 148 SMs x 2 CTAs

#define QSCALE 0.18033688f           // 0.125 * log2(e)

template<int N, int MODE>
__global__ __launch_bounds__(256, 2)
void gemm16(const __half* __restrict__ A, const __half* __restrict__ Bt,
            const float* __restrict__ bias,
            void* __restrict__ O0, void* __restrict__ O1, void* __restrict__ O2)
{
    extern __shared__ uint32_t sw[];
    const int tid  = threadIdx.x;
    const int w    = tid >> 5;
    const int lane = tid & 31;
    const int g    = lane >> 2;
    const int t    = lane & 3;
    const int wm   = (w >> 2) * 64;
    const int wn   = (w & 3) * 32;
    const int bid  = blockIdx.x;
    const uint32_t smem_base = smem_u32(sw);

    const int NX = N / 128;
    const int total_tiles = (MM / 128) * NX;
    const int G = gridDim.x;
    if (bid >= total_tiles) return;
    const int ntiles = (total_tiles - 1 - bid) / G + 1;
    const int slabs_total = ntiles * 16;

    const int l7        = lane & 7;
    const int a_row_off = l7 + ((lane & 8) ? 8 : 0);
    const int a_col4    = ((lane >> 4) & 1) * 4;
    const int sel       = lane >> 3;
    const int b_row_off = l7 + ((sel & 2) ? 8 : 0);
    const int b_col4    = (sel & 1) * 4;

    // issue slab q into pipeline stage st
    auto issueq = [&](int q, int st) {
        const int tq = bid + (q >> 4) * G;
        const int bm = (tq / NX) * 128;
        const int bn = (tq % NX) * 128;
        const int k0 = (q & 15) * 64;
        const uint32_t baseA = smem_base + (uint32_t)st * STG_WORDS * 4;
        const uint32_t baseB = baseA + TILE_WORDS * 4;
#pragma unroll
        for (int r = 0; r < 4; r++) {
            const int i   = tid + r * 256;     // chunk index, 1024 per tile
            const int row = i >> 3;
            const int c   = i & 7;
            cp16(baseA + (row * LSTR + c * 4) * 4,
                 &A[(size_t)(bm + row) * 1024 + k0 + c * 8]);
            cp16(baseB + (row * LSTR + c * 4) * 4,
                 &Bt[(size_t)(bn + row) * 1024 + k0 + c * 8]);
        }
        CP_COMMIT();
    };

    issueq(0, 0);
    issueq(1, 1);                    // PIPE-1 outstanding

    float acc[4][4][4];
#pragma unroll
    for (int mi = 0; mi < 4; mi++)
#pragma unroll
        for (int ni = 0; ni < 4; ni++)
#pragma unroll
            for (int c = 0; c < 4; c++) acc[mi][ni][c] = 0.f;

    for (int q = 0; q < slabs_total; q++) {
        CP_WAIT(PIPE - 2);           // slab q resident
        __syncthreads();             // all warps done with slab q-1's slot
        const uint32_t As_b = smem_base + (uint32_t)(q % PIPE) * STG_WORDS * 4;
        const uint32_t Bs_b = As_b + TILE_WORDS * 4;
#pragma unroll
        for (int kk = 0; kk < 4; kk++) {
            unsigned a[4][4];
#pragma unroll
            for (int mi = 0; mi < 4; mi++)
                ldsm4(a[mi], As_b + (((wm + mi * 16) + a_row_off) * LSTR
                                     + a_col4 + kk * 8) * 4);
            unsigned b[2][4];
#pragma unroll
            for (int nip = 0; nip < 2; nip++)
                ldsm4(b[nip], Bs_b + (((wn + nip * 16) + b_row_off) * LSTR
                                      + b_col4 + kk * 8) * 4);
#pragma unroll
            for (int nip = 0; nip < 2; nip++)
#pragma unroll
                for (int mi = 0; mi < 4; mi++) {
                    mma_f16(acc[mi][2 * nip],     a[mi], b[nip][0], b[nip][1]);
                    mma_f16(acc[mi][2 * nip + 1], a[mi], b[nip][2], b[nip][3]);
                }
            if (kk == 0 && q + PIPE - 1 < slabs_total)
                issueq(q + PIPE - 1, (q + PIPE - 1) % PIPE);
        }

        if ((q & 15) == 15) {
            // ---- tile epilogue (reg -> global, no barrier) ----
            const int tq = bid + (q >> 4) * G;
            const int bm = (tq / NX) * 128;
            const int bn = (tq % NX) * 128;
#pragma unroll
            for (int mi = 0; mi < 4; mi++) {
#pragma unroll
                for (int ni = 0; ni < 4; ni++) {
                    const int r0 = bm + wm + mi * 16 + g;
                    const int c0 = bn + wn + ni * 8 + 2 * t;
                    const float b0 = bias[c0], b1 = bias[c0 + 1];
                    float v00 = acc[mi][ni][0] + b0, v01 = acc[mi][ni][1] + b1;
                    float v10 = acc[mi][ni][2] + b0, v11 = acc[mi][ni][3] + b1;
                    if (MODE == 0) {
                        float* O = (float*)O0;
                        *(float2*)&O[(size_t)r0 * N + c0]       = make_float2(v00, v01);
                        *(float2*)&O[(size_t)(r0 + 8) * N + c0] = make_float2(v10, v11);
                    } else {
                        const int sec = c0 >> 10;          // 0=q,1=k,2=v
                        const int cc  = c0 & 1023;
                        const int h   = cc >> 6;
                        const int d   = cc & 63;
                        __half* dst = (sec == 0) ? (__half*)O0
                                    : (sec == 1) ? (__half*)O1 : (__half*)O2;
                        const float sc = (sec == 0) ? QSCALE : 1.0f;
                        {
                            const int m = r0;
                            const size_t o = (((size_t)((m >> 11) * HH + h)) * TT + (m & 2047)) * DHD + d;
                            *(unsigned*)&dst[o] = h2u(v00 * sc, v01 * sc);
                        }
                        {
                            const int m = r0 + 8;
                            const size_t o = (((size_t)((m >> 11) * HH + h)) * TT + (m & 2047)) * DHD + d;
                            *(unsigned*)&dst[o] = h2u(v10 * sc, v11 * sc);
                        }
                    }
                    // reset accumulator for next tile
                    acc[mi][ni][0] = 0.f; acc[mi][ni][1] = 0.f;
                    acc[mi][ni][2] = 0.f; acc[mi][ni][3] = 0.f;
                }
            }
        }
    }
}

// ---------------------------------------------------------------------------
// Causal flash attention, fp16 mma m16n8k16, exp2-domain softmax with
// ex2.approx.f16x2 (p computed directly as fp16 pairs = PV A-fragments).
// K/V double-buffered via cp.async; V via ldmatrix.x4.trans.
// Causal warp-skip: warps whose 16 query rows are entirely below the key
// tile skip all math (identity on m/l/O) but still run barriers/cp.async.
// Block = 128 queries of one (b,h). 256 threads = 8 warps x 16 rows.
// ---------------------------------------------------------------------------
#define AST 36
#define KV_TILE_WORDS (64*AST)
#define ATT_WORDS (128*AST + 4*KV_TILE_WORDS)   // Q + 2 stages x (K,V)
#define ATT_SMEM_BYTES (ATT_WORDS * 4)

__global__ __launch_bounds__(256, 2)
void attn16(__half* __restrict__ O)
{
    extern __shared__ uint32_t sm[];
    uint32_t* Qs = sm;                           // [128][36]

    const int tid  = threadIdx.x;
    const int w    = tid >> 5;
    const int lane = tid & 31;
    const int g    = lane >> 2;
    const int t    = lane & 3;
    const int bh   = blockIdx.y;                 // 0..63
    const int qt   = (gridDim.x - 1) - blockIdx.x;   // heavy tiles first
    const int b    = bh >> 4;
    const int h    = bh & 15;
    const size_t base = (size_t)bh * TT * DHD;
    const int q0   = qt * 128;
    const int rw   = w * 16;

    const uint32_t qs_byte  = smem_u32(sm);
    const uint32_t kv0_byte = qs_byte + 128 * AST * 4;   // stage0 K

    const int l7        = lane & 7;
    const int a_row_off = l7 + ((lane & 8) ? 8 : 0);
    const int a_col4    = ((lane >> 4) & 1) * 4;
    const int sel       = lane >> 3;
    const int b_row_off = l7 + ((sel & 2) ? 8 : 0);
    const int b_col4    = (sel & 1) * 4;
    const int v_row_off = l7 + ((sel & 1) ? 8 : 0);
    const int v_col_b   = (sel >> 1) * 16;

    const int krow = tid >> 2;                   // 0..63
    const int kc0  = (tid & 3) * 2;

    auto issue_kv = [&](int kt, int st) {
        const uint32_t kb = kv0_byte + (uint32_t)st * 2 * KV_TILE_WORDS * 4;
        const uint32_t vb = kb + KV_TILE_WORDS * 4;
        const size_t go = base + (size_t)(kt * 64 + krow) * DHD;
        cp16(kb + (krow * AST + kc0 * 4) * 4,       &g_K16[go + kc0 * 8]);
        cp16(kb + (krow * AST + (kc0 + 1) * 4) * 4, &g_K16[go + (kc0 + 1) * 8]);
        cp16(vb + (krow * AST + kc0 * 4) * 4,       &g_V16[go + kc0 * 8]);
        cp16(vb + (krow * AST + (kc0 + 1) * 4) * 4, &g_V16[go + (kc0 + 1) * 8]);
        CP_COMMIT();
    };

    issue_kv(0, 0);

    // Load Q tile (scaled by 0.125*log2e in GEMM epilogue)
#pragma unroll
    for (int it = 0; it < 4; it++) {
        const int i   = tid + it * 256;
        const int row = i >> 3;
        const int c   = i & 7;
        *(uint4*)&Qs[row * AST + c * 4] =
            *(const uint4*)&g_Q16[base + (size_t)(q0 + row) * DHD + c * 8];
    }

    float m0 = -INFINITY, m1 = -INFINITY, l0 = 0.f, l1 = 0.f;
    float oacc[8][4];
#pragma unroll
    for (int j = 0; j < 8; j++)
#pragma unroll
        for (int c = 0; c < 4; c++) oacc[j][c] = 0.f;

    const int ktmax = 2 * qt + 1;
    for (int kt = 0; kt <= ktmax; kt++) {
        const int k0g = kt * 64;
        CP_WAIT(0);
        __syncthreads();
        if (kt < ktmax) issue_kv(kt + 1, (kt + 1) & 1);

        // causal warp-skip: this warp's rows all precede the key tile?
        if (k0g > q0 + rw + 15) continue;

        const uint32_t ks_byte = kv0_byte + (uint32_t)(kt & 1) * 2 * KV_TILE_WORDS * 4;
        const uint32_t vs_byte = ks_byte + KV_TILE_WORDS * 4;

        // ---- S = Q K^T (log2-domain; Q pre-scaled) ----
        float sacc[8][4];
#pragma unroll
        for (int j = 0; j < 8; j++)
#pragma unroll
            for (int c = 0; c < 4; c++) sacc[j][c] = 0.f;

#pragma unroll
        for (int kk = 0; kk < 4; kk++) {
            unsigned a[4];
            ldsm4(a, qs_byte + ((rw + a_row_off) * AST + a_col4 + kk * 8) * 4);
#pragma unroll
            for (int jp = 0; jp < 4; jp++) {
                unsigned bb[4];
                ldsm4(bb, ks_byte + ((jp * 16 + b_row_off) * AST
                                     + b_col4 + kk * 8) * 4);
                mma_f16(sacc[2 * jp],     a, bb[0], bb[1]);
                mma_f16(sacc[2 * jp + 1], a, bb[2], bb[3]);
            }
        }

        // ---- causal mask ----
        if (k0g + 63 > q0 + rw) {
            const int gr0 = q0 + rw + g, gr1 = gr0 + 8;
#pragma unroll
            for (int j = 0; j < 8; j++) {
                const int gc = k0g + j * 8 + 2 * t;
                if (gc     > gr0) sacc[j][0] = -INFINITY;
                if (gc + 1 > gr0) sacc[j][1] = -INFINITY;
                if (gc     > gr1) sacc[j][2] = -INFINITY;
                if (gc + 1 > gr1) sacc[j][3] = -INFINITY;
            }
        }

        // ---- online softmax (exp2 domain; rows rw+g, rw+g+8) ----
        float mt0 = -INFINITY, mt1 = -INFINITY;
#pragma unroll
        for (int j = 0; j < 8; j++) {
            mt0 = fmaxf(mt0, fmaxf(sacc[j][0], sacc[j][1]));
            mt1 = fmaxf(mt1, fmaxf(sacc[j][2], sacc[j][3]));
        }
        // packed half2 max reduction across the 4 lanes of each row
        {
            unsigned mp = h2u(mt0, mt1);
            unsigned o1 = __shfl_xor_sync(0xffffffffu, mp, 1);
            __half2 hm = __hmax2(*(__half2*)&mp, *(__half2*)&o1);
            unsigned m2u = *(unsigned*)&hm;
            unsigned o2 = __shfl_xor_sync(0xffffffffu, m2u, 2);
            hm = __hmax2(*(__half2*)&m2u, *(__half2*)&o2);
            const float2 mf = __half22float2(hm);
            mt0 = mf.x; mt1 = mf.y;
        }

        const float mn0 = fmaxf(m0, mt0), mn1 = fmaxf(m1, mt1);
        const float cor0 = exp2f(m0 - mn0), cor1 = exp2f(m1 - mn1);

        // p = 2^(s - m), computed as fp16 pairs -> directly the PV A-fragments
        unsigned pa[4][4];
        float ls0 = 0.f, ls1 = 0.f;
#pragma unroll
        for (int j = 0; j < 8; j++) {
            const unsigned p01 = ex2h2(h2u(sacc[j][0] - mn0, sacc[j][1] - mn0));
            const unsigned p23 = ex2h2(h2u(sacc[j][2] - mn1, sacc[j][3] - mn1));
            const float2 f01 = __half22float2(*(const __half2*)&p01);
            const float2 f23 = __half22float2(*(const __half2*)&p23);
            ls0 += f01.x + f01.y;
            ls1 += f23.x + f23.y;
            pa[j >> 1][(j & 1) * 2 + 0] = p01;
            pa[j >> 1][(j & 1) * 2 + 1] = p23;
        }
        ls0 += __shfl_xor_sync(0xffffffffu, ls0, 1);
        ls0 += __shfl_xor_sync(0xffffffffu, ls0, 2);
        ls1 += __shfl_xor_sync(0xffffffffu, ls1, 1);
        ls1 += __shfl_xor_sync(0xffffffffu, ls1, 2);

        l0 = l0 * cor0 + ls0;  m0 = mn0;
        l1 = l1 * cor1 + ls1;  m1 = mn1;
#pragma unroll
        for (int j = 0; j < 8; j++) {
            oacc[j][0] *= cor0; oacc[j][1] *= cor0;
            oacc[j][2] *= cor1; oacc[j][3] *= cor1;
        }

        // ---- O += P V ---- (B via ldmatrix.trans of V[key][d])
#pragma unroll
        for (int kk = 0; kk < 4; kk++) {
#pragma unroll
            for (int jp = 0; jp < 4; jp++) {
                unsigned bb[4];
                ldsm4t(bb, vs_byte + ((kk * 16 + v_row_off) * AST) * 4
                                   + jp * 32 + v_col_b);
                mma_f16(oacc[2 * jp],     pa[kk], bb[0], bb[1]);
                mma_f16(oacc[2 * jp + 1], pa[kk], bb[2], bb[3]);
            }
        }
    }

    // ---- normalize, write fp16 g_O [B,T,C] ----
    const float inv0 = 1.0f / l0, inv1 = 1.0f / l1;
    const int qrow = q0 + rw + g;
    const size_t ob0 = ((size_t)b * TT + qrow)     * CC + h * DHD;
    const size_t ob1 = ((size_t)b * TT + qrow + 8) * CC + h * DHD;
#pragma unroll
    for (int j = 0; j < 8; j++) {
        const int c = j * 8 + 2 * t;
        *(unsigned*)&O[ob0 + c] = h2u(oacc[j][0] * inv0, oacc[j][1] * inv0);
        *(unsigned*)&O[ob1 + c] = h2u(oacc[j][2] * inv1, oacc[j][3] * inv1);
    }
}

// ---------------------------------------------------------------------------
extern "C" void kernel_launch(void* const* d_in, const int* in_sizes, int n_in,
                              void* d_out, int out_size)
{
    const float* x     = (const float*)d_in[0];   // [4,2048,1024]
    const float* W_qkv = (const float*)d_in[1];   // [1024,3072]
    const float* b_qkv = (const float*)d_in[2];   // [3072]
    const float* W_out = (const float*)d_in[3];   // [1024,1024]
    const float* b_out = (const float*)d_in[4];   // [1024]
    float* out = (float*)d_out;                   // [4,2048,1024]

    void *pX, *pQ, *pK, *pV, *pO, *pWq, *pWo;
    cudaGetSymbolAddress(&pX,  g_x16);
    cudaGetSymbolAddress(&pQ,  g_Q16);
    cudaGetSymbolAddress(&pK,  g_K16);
    cudaGetSymbolAddress(&pV,  g_V16);
    cudaGetSymbolAddress(&pO,  g_O16);
    cudaGetSymbolAddress(&pWq, g_Wq16);
    cudaGetSymbolAddress(&pWo, g_Wo16);

    cudaFuncSetAttribute(attn16, cudaFuncAttributeMaxDynamicSharedMemorySize,
                         ATT_SMEM_BYTES);
    cudaFuncSetAttribute(gemm16<3072,1>,
                         cudaFuncAttributeMaxDynamicSharedMemorySize, GEMM_SMEM);
    cudaFuncSetAttribute(gemm16<1024,0>,
                         cudaFuncAttributeMaxDynamicSharedMemorySize, GEMM_SMEM);

    // 0) Pre-pass: x -> fp16, weights -> fp16 transposed [N,K]
    f2h_k<<<(MM * CC) / (256 * 8), 256>>>(x, (__half*)pX);
    transpose_h<<<dim3(3072/32, 1024/32), 256>>>(W_qkv, (__half*)pWq, 1024, 3072);
    transpose_h<<<dim3(1024/32, 1024/32), 256>>>(W_out, (__half*)pWo, 1024, 1024);

    // 1) QKV projection (persistent fp16 GEMM, continuous pipeline)
    {
        gemm16<3072,1><<<GPERS, 256, GEMM_SMEM>>>((const __half*)pX,
                                                  (const __half*)pWq, b_qkv,
                                                  pQ, pK, pV);
    }
    // 2) Causal flash attention -> g_O16 [B,T,C]
    {
        dim3 grid(TT / 128, BB * HH);
        attn16<<<grid, 256, ATT_SMEM_BYTES>>>((__half*)pO);
    }
    // 3) Output projection (persistent) -> d_out (fp32)
    {
        gemm16<1024,0><<<GPERS, 256, GEMM_SMEM>>>((const __half*)pO,
                                                  (const __half*)pWo, b_out,
                                                  out, nullptr, nullptr);
    }
}